// round 16
// baseline (speedup 1.0000x reference)
#include <cuda_runtime.h>
#include <math_constants.h>

// Problem constants (dataset-fixed): N = 262144 rows, C = 1000 classes.
#define CE_MAXCTAS 65536   // >= ceil(N/8) for the benched shape (32768)

__device__ float g_cta_loss[CE_MAXCTAS];
__device__ unsigned int g_done_count = 0;   // reset by last CTA each run

// ---------------------------------------------------------------------------
// Deterministic single-pass fused cross-entropy, C == 1000 specialization.
//
// Phase A (all CTAs): ONE WARP per row, 8 rows per CTA.
//   Lane l owns cols {k*128 + l*4 .. +3}, k = 0..7 (compile-time bounds).
//   8 front-batched LDG.128 (.cs) per lane -> warp max -> warp sum(exp) ->
//   row loss; label logit pulled from registers (SEL chain + shfl).
//   CTA folds its 8 row losses -> g_cta_loss[blockIdx.x].
//
// Phase B (LAST CTA only, threadfence-reduction pattern): re-reads all
//   per-CTA sums with __ldcg in FIXED array order (bitwise deterministic,
//   independent of completion order), writes out = sum / N, resets counter.
// ---------------------------------------------------------------------------
__global__ __launch_bounds__(256, 4)
void ce_fused_c1000_kernel(const float* __restrict__ logits,
                           const long long* __restrict__ labels,
                           float* __restrict__ out, int N)
{
    const int lane = threadIdx.x & 31;
    const int warp = threadIdx.x >> 5;
    const int row  = (blockIdx.x << 3) + warp;   // 8 warps per CTA

    __shared__ float sh[8];
    __shared__ bool  s_last;

    // ---------------- Phase A: per-row loss ----------------
    float rowloss = 0.0f;
    if (row < N) {
        const float* rowp = logits + (long long)row * 1000LL;

        const int lab = (int)labels[row];        // uniform within warp

        float4 v[8];
        #pragma unroll
        for (int k = 0; k < 7; ++k)
            v[k] = __ldcs(reinterpret_cast<const float4*>(rowp + (k << 7) + (lane << 2)));
        if (lane < 26)
            v[7] = __ldcs(reinterpret_cast<const float4*>(rowp + 896 + (lane << 2)));
        else
            v[7] = make_float4(-CUDART_INF_F, -CUDART_INF_F,
                               -CUDART_INF_F, -CUDART_INF_F);

        // label logit from registers
        const int klab = lab >> 7;
        const int elab = lab & 3;
        const int slab = (lab >> 2) & 31;
        float4 w = v[0];
        #pragma unroll
        for (int k = 1; k < 8; ++k)
            if (klab == k) w = v[k];
        float val = (elab == 0) ? w.x : (elab == 1) ? w.y : (elab == 2) ? w.z : w.w;
        const float xlab = __shfl_sync(0xffffffffu, val, slab);

        // warp max
        float m = -CUDART_INF_F;
        #pragma unroll
        for (int k = 0; k < 8; ++k)
            m = fmaxf(m, fmaxf(fmaxf(v[k].x, v[k].y), fmaxf(v[k].z, v[k].w)));
        #pragma unroll
        for (int off = 16; off > 0; off >>= 1)
            m = fmaxf(m, __shfl_xor_sync(0xffffffffu, m, off));

        // warp sum of exp(x - m); -INF fills contribute 0
        float s = 0.0f;
        #pragma unroll
        for (int k = 0; k < 8; ++k)
            s += __expf(v[k].x - m) + __expf(v[k].y - m)
               + __expf(v[k].z - m) + __expf(v[k].w - m);
        #pragma unroll
        for (int off = 16; off > 0; off >>= 1)
            s += __shfl_xor_sync(0xffffffffu, s, off);

        rowloss = __logf(s) + m - xlab;          // positive loss = -logp[label]
    }

    // per-CTA sum of 8 row losses
    if (lane == 0) sh[warp] = rowloss;
    __syncthreads();
    if (threadIdx.x == 0) {
        float c = 0.0f;
        #pragma unroll
        for (int k = 0; k < 8; ++k) c += sh[k];
        g_cta_loss[blockIdx.x] = c;
        __threadfence();                         // publish before counting
        const unsigned int prev = atomicAdd(&g_done_count, 1u);
        s_last = (prev == (unsigned int)gridDim.x - 1u);
    }
    __syncthreads();

    // ---------------- Phase B: last CTA folds everything ----------------
    if (s_last) {
        const int tid  = threadIdx.x;
        const int nCTA = gridDim.x;
        float s = 0.0f;

        const int nvec = nCTA >> 2;
        const float4* p4 = reinterpret_cast<const float4*>(g_cta_loss);
        for (int i = tid; i < nvec; i += 256) {
            const float4 u = __ldcg(p4 + i);     // L2 (coherent) read
            s += (u.x + u.y) + (u.z + u.w);
        }
        for (int i = (nvec << 2) + tid; i < nCTA; i += 256)
            s += __ldcg(g_cta_loss + i);

        // block sum, fixed tree order
        __shared__ float sh2[8];
        #pragma unroll
        for (int off = 16; off > 0; off >>= 1)
            s += __shfl_xor_sync(0xffffffffu, s, off);
        if (lane == 0) sh2[warp] = s;
        __syncthreads();
        if (threadIdx.x == 0) {
            float r = 0.0f;
            #pragma unroll
            for (int k = 0; k < 8; ++k) r += sh2[k];
            out[0] = r / (float)N;
            g_done_count = 0;                    // reset for next graph replay
        }
    }
}

// ---------------------------------------------------------------------------
// Generic fallback (any C): warp per row, online softmax, scalar loads, same
// threadfence-reduction finish. Correctness-only path.
// ---------------------------------------------------------------------------
__global__ __launch_bounds__(256)
void ce_fused_generic_kernel(const float* __restrict__ logits,
                             const long long* __restrict__ labels,
                             float* __restrict__ out, int C, int N)
{
    const int lane = threadIdx.x & 31;
    const int warp = threadIdx.x >> 5;
    const int row  = (blockIdx.x << 3) + warp;

    __shared__ float sh[8];
    __shared__ bool  s_last;

    float rowloss = 0.0f;
    if (row < N) {
        const float* rowp = logits + (long long)row * (long long)C;
        const int lab = (int)labels[row];

        float m = -CUDART_INF_F, s = 0.0f;
        for (int col = lane; col < C; col += 32) {
            const float x = rowp[col];
            const float mn = fmaxf(m, x);
            s = s * __expf(m - mn) + __expf(x - mn);
            m = mn;
        }
        #pragma unroll
        for (int off = 16; off > 0; off >>= 1) {
            const float mo = __shfl_xor_sync(0xffffffffu, m, off);
            const float so = __shfl_xor_sync(0xffffffffu, s, off);
            const float mn = fmaxf(m, mo);
            s = s * __expf(m - mn) + so * __expf(mo - mn);
            m = mn;
        }
        float xlab = 0.0f;
        if (lane == 0) xlab = rowp[lab];
        rowloss = __logf(s) + m - xlab;          // valid in lane 0
    }

    if (lane == 0) sh[warp] = rowloss;
    __syncthreads();
    if (threadIdx.x == 0) {
        float c = 0.0f;
        #pragma unroll
        for (int k = 0; k < 8; ++k) c += sh[k];
        g_cta_loss[blockIdx.x] = c;
        __threadfence();
        const unsigned int prev = atomicAdd(&g_done_count, 1u);
        s_last = (prev == (unsigned int)gridDim.x - 1u);
    }
    __syncthreads();

    if (s_last) {
        const int tid  = threadIdx.x;
        const int nCTA = gridDim.x;
        float s = 0.0f;
        for (int i = tid; i < nCTA; i += 256)
            s += __ldcg(g_cta_loss + i);

        __shared__ float sh2[8];
        #pragma unroll
        for (int off = 16; off > 0; off >>= 1)
            s += __shfl_xor_sync(0xffffffffu, s, off);
        if (lane == 0) sh2[warp] = s;
        __syncthreads();
        if (threadIdx.x == 0) {
            float r = 0.0f;
            #pragma unroll
            for (int k = 0; k < 8; ++k) r += sh2[k];
            out[0] = r / (float)N;
            g_done_count = 0;
        }
    }
}

// ---------------------------------------------------------------------------
extern "C" void kernel_launch(void* const* d_in, const int* in_sizes, int n_in,
                              void* d_out, int out_size)
{
    const float*     logits = (const float*)d_in[0];
    const long long* labels = (const long long*)d_in[1];
    float*           out    = (float*)d_out;

    const int N = in_sizes[1];                 // 262144
    const int C = in_sizes[0] / N;             // 1000

    const int grid = (N + 7) / 8;              // 8 warps (rows) per CTA

    if (C == 1000)
        ce_fused_c1000_kernel<<<grid, 256>>>(logits, labels, out, N);
    else
        ce_fused_generic_kernel<<<grid, 256>>>(logits, labels, out, C, N);
}

// round 17
// speedup vs baseline: 1.0010x; 1.0010x over previous
#include <cuda_runtime.h>
#include <math_constants.h>

// Problem constants (dataset-fixed): N = 262144 rows, C = 1000 classes.
#define CE_MAXCTAS 65536   // >= ceil(N/8) for the benched shape (32768)

__device__ float g_cta_loss[CE_MAXCTAS];
__device__ unsigned int g_done_count = 0;   // reset by last CTA each run

// ---------------------------------------------------------------------------
// Deterministic single-pass fused cross-entropy, C == 1000 specialization.
//
// Phase A (all CTAs): ONE WARP per row, 8 rows per CTA.
//   Lane l owns cols {k*128 + l*4 .. +3}, k = 0..7 (compile-time bounds).
//   8 front-batched LDG.128 (.cs) per lane -> warp max -> warp sum(exp) ->
//   row loss; label logit pulled from registers (SEL chain + shfl).
//   CTA folds its 8 row losses -> g_cta_loss[blockIdx.x].
//
// Phase B (LAST CTA only, threadfence-reduction pattern): re-reads all
//   per-CTA sums with __ldcg in FIXED array order (bitwise deterministic,
//   independent of completion order), writes out = sum / N, resets counter.
// ---------------------------------------------------------------------------
__global__ __launch_bounds__(256, 4)
void ce_fused_c1000_kernel(const float* __restrict__ logits,
                           const long long* __restrict__ labels,
                           float* __restrict__ out, int N)
{
    const int lane = threadIdx.x & 31;
    const int warp = threadIdx.x >> 5;
    const int row  = (blockIdx.x << 3) + warp;   // 8 warps per CTA

    __shared__ float sh[8];
    __shared__ bool  s_last;

    // ---------------- Phase A: per-row loss ----------------
    float rowloss = 0.0f;
    if (row < N) {
        const float* rowp = logits + (long long)row * 1000LL;

        const int lab = (int)labels[row];        // uniform within warp

        float4 v[8];
        #pragma unroll
        for (int k = 0; k < 7; ++k)
            v[k] = __ldcs(reinterpret_cast<const float4*>(rowp + (k << 7) + (lane << 2)));
        if (lane < 26)
            v[7] = __ldcs(reinterpret_cast<const float4*>(rowp + 896 + (lane << 2)));
        else
            v[7] = make_float4(-CUDART_INF_F, -CUDART_INF_F,
                               -CUDART_INF_F, -CUDART_INF_F);

        // label logit from registers
        const int klab = lab >> 7;
        const int elab = lab & 3;
        const int slab = (lab >> 2) & 31;
        float4 w = v[0];
        #pragma unroll
        for (int k = 1; k < 8; ++k)
            if (klab == k) w = v[k];
        float val = (elab == 0) ? w.x : (elab == 1) ? w.y : (elab == 2) ? w.z : w.w;
        const float xlab = __shfl_sync(0xffffffffu, val, slab);

        // warp max
        float m = -CUDART_INF_F;
        #pragma unroll
        for (int k = 0; k < 8; ++k)
            m = fmaxf(m, fmaxf(fmaxf(v[k].x, v[k].y), fmaxf(v[k].z, v[k].w)));
        #pragma unroll
        for (int off = 16; off > 0; off >>= 1)
            m = fmaxf(m, __shfl_xor_sync(0xffffffffu, m, off));

        // warp sum of exp(x - m); -INF fills contribute 0
        float s = 0.0f;
        #pragma unroll
        for (int k = 0; k < 8; ++k)
            s += __expf(v[k].x - m) + __expf(v[k].y - m)
               + __expf(v[k].z - m) + __expf(v[k].w - m);
        #pragma unroll
        for (int off = 16; off > 0; off >>= 1)
            s += __shfl_xor_sync(0xffffffffu, s, off);

        rowloss = __logf(s) + m - xlab;          // positive loss = -logp[label]
    }

    // per-CTA sum of 8 row losses
    if (lane == 0) sh[warp] = rowloss;
    __syncthreads();
    if (threadIdx.x == 0) {
        float c = 0.0f;
        #pragma unroll
        for (int k = 0; k < 8; ++k) c += sh[k];
        g_cta_loss[blockIdx.x] = c;
        __threadfence();                         // publish before counting
        const unsigned int prev = atomicAdd(&g_done_count, 1u);
        s_last = (prev == (unsigned int)gridDim.x - 1u);
    }
    __syncthreads();

    // ---------------- Phase B: last CTA folds everything ----------------
    if (s_last) {
        const int tid  = threadIdx.x;
        const int nCTA = gridDim.x;
        float s = 0.0f;

        const int nvec = nCTA >> 2;
        const float4* p4 = reinterpret_cast<const float4*>(g_cta_loss);
        for (int i = tid; i < nvec; i += 256) {
            const float4 u = __ldcg(p4 + i);     // L2 (coherent) read
            s += (u.x + u.y) + (u.z + u.w);
        }
        for (int i = (nvec << 2) + tid; i < nCTA; i += 256)
            s += __ldcg(g_cta_loss + i);

        // block sum, fixed tree order
        __shared__ float sh2[8];
        #pragma unroll
        for (int off = 16; off > 0; off >>= 1)
            s += __shfl_xor_sync(0xffffffffu, s, off);
        if (lane == 0) sh2[warp] = s;
        __syncthreads();
        if (threadIdx.x == 0) {
            float r = 0.0f;
            #pragma unroll
            for (int k = 0; k < 8; ++k) r += sh2[k];
            out[0] = r / (float)N;
            g_done_count = 0;                    // reset for next graph replay
        }
    }
}

// ---------------------------------------------------------------------------
// Generic fallback (any C): warp per row, online softmax, scalar loads, same
// threadfence-reduction finish. Correctness-only path.
// ---------------------------------------------------------------------------
__global__ __launch_bounds__(256)
void ce_fused_generic_kernel(const float* __restrict__ logits,
                             const long long* __restrict__ labels,
                             float* __restrict__ out, int C, int N)
{
    const int lane = threadIdx.x & 31;
    const int warp = threadIdx.x >> 5;
    const int row  = (blockIdx.x << 3) + warp;

    __shared__ float sh[8];
    __shared__ bool  s_last;

    float rowloss = 0.0f;
    if (row < N) {
        const float* rowp = logits + (long long)row * (long long)C;
        const int lab = (int)labels[row];

        float m = -CUDART_INF_F, s = 0.0f;
        for (int col = lane; col < C; col += 32) {
            const float x = rowp[col];
            const float mn = fmaxf(m, x);
            s = s * __expf(m - mn) + __expf(x - mn);
            m = mn;
        }
        #pragma unroll
        for (int off = 16; off > 0; off >>= 1) {
            const float mo = __shfl_xor_sync(0xffffffffu, m, off);
            const float so = __shfl_xor_sync(0xffffffffu, s, off);
            const float mn = fmaxf(m, mo);
            s = s * __expf(m - mn) + so * __expf(mo - mn);
            m = mn;
        }
        float xlab = 0.0f;
        if (lane == 0) xlab = rowp[lab];
        rowloss = __logf(s) + m - xlab;          // valid in lane 0
    }

    if (lane == 0) sh[warp] = rowloss;
    __syncthreads();
    if (threadIdx.x == 0) {
        float c = 0.0f;
        #pragma unroll
        for (int k = 0; k < 8; ++k) c += sh[k];
        g_cta_loss[blockIdx.x] = c;
        __threadfence();
        const unsigned int prev = atomicAdd(&g_done_count, 1u);
        s_last = (prev == (unsigned int)gridDim.x - 1u);
    }
    __syncthreads();

    if (s_last) {
        const int tid  = threadIdx.x;
        const int nCTA = gridDim.x;
        float s = 0.0f;
        for (int i = tid; i < nCTA; i += 256)
            s += __ldcg(g_cta_loss + i);

        __shared__ float sh2[8];
        #pragma unroll
        for (int off = 16; off > 0; off >>= 1)
            s += __shfl_xor_sync(0xffffffffu, s, off);
        if (lane == 0) sh2[warp] = s;
        __syncthreads();
        if (threadIdx.x == 0) {
            float r = 0.0f;
            #pragma unroll
            for (int k = 0; k < 8; ++k) r += sh2[k];
            out[0] = r / (float)N;
            g_done_count = 0;
        }
    }
}

// ---------------------------------------------------------------------------
extern "C" void kernel_launch(void* const* d_in, const int* in_sizes, int n_in,
                              void* d_out, int out_size)
{
    const float*     logits = (const float*)d_in[0];
    const long long* labels = (const long long*)d_in[1];
    float*           out    = (float*)d_out;

    const int N = in_sizes[1];                 // 262144
    const int C = in_sizes[0] / N;             // 1000

    const int grid = (N + 7) / 8;              // 8 warps (rows) per CTA

    if (C == 1000)
        ce_fused_c1000_kernel<<<grid, 256>>>(logits, labels, out, N);
    else
        ce_fused_generic_kernel<<<grid, 256>>>(logits, labels, out, C, N);
}